// round 1
// baseline (speedup 1.0000x reference)
#include <cuda_runtime.h>
#include <cuda_bf16.h>

// Problem constants (fixed by reference)
#define B_  64
#define D_  7
#define M_  4
#define S_  16
#define NF_ 1000
#define NC_ 5
#define SLOTS (D_ * M_ * S_)   // 448 slots per batch

// Deterministic per-batch scratch (no device allocation allowed)
__device__ float g_partial[B_];

// Kernel 1: one block per batch element. Each thread owns one (d,m,s) slot.
// Key insight: ids are exact integers after rounding, so the Gaussian soft
// lookup exp(-100*k^2) is a one-hot gather (tail weight ~3.7e-44, negligible
// vs 1e-3 tolerance). We gather data[id][0..4] directly from a smem-staged
// copy of the 1000x5 table.
__global__ __launch_bounds__(SLOTS)
void nutrition_per_batch(const float* __restrict__ y_pred,
                         const float* __restrict__ y,
                         const float* __restrict__ data) {
    __shared__ float stab[NF_ * NC_];          // 20000 B
    __shared__ float wsum[SLOTS / 32][NC_];    // 14 warps x 5 cats

    const int b = blockIdx.x;
    const int t = threadIdx.x;                 // 0..447
    const int lane = t & 31;
    const int wid  = t >> 5;

    // Stage nutrition table into shared (vectorized-ish; 5000 floats / 448 thr)
    #pragma unroll
    for (int i = t; i < NF_ * NC_; i += SLOTS) stab[i] = data[i];
    __syncthreads();

    // Each slot is a (id, amt) float2 pair in the last axis.
    const float2* yp = reinterpret_cast<const float2*>(y_pred) + (size_t)b * SLOTS;
    const float2* yt = reinterpret_cast<const float2*>(y)      + (size_t)b * SLOTS;
    const float2 p = yp[t];
    const float2 g = yt[t];

    // jnp.round == round-half-to-even == rintf default mode.
    int pid = (int)rintf(p.x);
    int tid = (int)rintf(g.x);
    pid = min(max(pid, 0), NF_ - 1);
    tid = min(max(tid, 0), NF_ - 1);

    const float pamt = p.y;
    const float tamt = g.y;
    const float* dp = &stab[pid * NC_];
    const float* dt = &stab[tid * NC_];

    float diff[NC_];
    #pragma unroll
    for (int c = 0; c < NC_; c++)
        diff[c] = dp[c] * pamt - dt[c] * tamt;

    // Warp reduction (5 categories)
    #pragma unroll
    for (int off = 16; off > 0; off >>= 1) {
        #pragma unroll
        for (int c = 0; c < NC_; c++)
            diff[c] += __shfl_down_sync(0xffffffffu, diff[c], off);
    }
    if (lane == 0) {
        #pragma unroll
        for (int c = 0; c < NC_; c++) wsum[wid][c] = diff[c];
    }
    __syncthreads();

    // Cross-warp reduce + abs + category sum in a single thread
    // (fixed order -> deterministic across graph replays).
    if (t == 0) {
        float s = 0.0f;
        #pragma unroll
        for (int c = 0; c < NC_; c++) {
            float a = 0.0f;
            #pragma unroll
            for (int w = 0; w < SLOTS / 32; w++) a += wsum[w][c];
            s += fabsf(a);
        }
        g_partial[b] = s;
    }
}

// Kernel 2: one warp sums the 64 per-batch values in a fixed order and
// applies all scaling: loss = 5 * mean_b( sum_c |diff| / (100 * 7) )
__global__ __launch_bounds__(32)
void nutrition_finalize(float* __restrict__ out) {
    const int t = threadIdx.x;
    float s = g_partial[t] + g_partial[t + 32];
    #pragma unroll
    for (int off = 16; off > 0; off >>= 1)
        s += __shfl_down_sync(0xffffffffu, s, off);
    if (t == 0)
        out[0] = s * (5.0f / (B_ * 100.0f * 7.0f));
}

extern "C" void kernel_launch(void* const* d_in, const int* in_sizes, int n_in,
                              void* d_out, int out_size) {
    const float* y_pred = (const float*)d_in[0];   // [B,D,M,S,2]
    const float* y      = (const float*)d_in[1];   // [B,D,M,S,2]
    const float* data   = (const float*)d_in[2];   // [NF,NC]
    float* out = (float*)d_out;

    nutrition_per_batch<<<B_, SLOTS>>>(y_pred, y, data);
    nutrition_finalize<<<1, 32>>>(out);
}

// round 2
// speedup vs baseline: 1.0295x; 1.0295x over previous
#include <cuda_runtime.h>
#include <cuda_bf16.h>

// Problem constants (fixed by reference)
#define B_  64
#define D_  7
#define M_  4
#define S_  16
#define NF_ 1000
#define NC_ 5
#define SLOTS (D_ * M_ * S_)   // 448 slots per batch
#define NWARPS (SLOTS / 32)    // 14

// Deterministic scratch (device allocation is forbidden)
__device__ float g_partial[B_];
__device__ unsigned int g_ticket;   // zero-initialized; last block resets it

// One block per batch element. Each thread owns one (d,m,s) slot.
// Key insight: ids are exact integers after rounding, so the Gaussian soft
// lookup exp(-100*k^2) collapses to a one-hot gather (tail weight ~3.7e-44).
// We gather data[id][0..4] straight from global: the 20KB table is fully
// L2-resident, so a direct gather (~234cyc L2 hit) beats per-block smem
// staging (serial DRAM loop + barrier in all 64 blocks).
// The last block to finish performs the cross-batch reduction in a fixed
// order (deterministic across graph replays) and resets the ticket.
__global__ __launch_bounds__(SLOTS)
void nutrition_fused(const float* __restrict__ y_pred,
                     const float* __restrict__ y,
                     const float* __restrict__ data,
                     float* __restrict__ out) {
    __shared__ float wsum[NWARPS][NC_];
    __shared__ unsigned int s_islast;

    const int b = blockIdx.x;
    const int t = threadIdx.x;                 // 0..447
    const int lane = t & 31;
    const int wid  = t >> 5;

    // Each slot is a (id, amt) float2 pair in the last axis.
    const float2 p = reinterpret_cast<const float2*>(y_pred)[b * SLOTS + t];
    const float2 g = reinterpret_cast<const float2*>(y)     [b * SLOTS + t];

    // jnp.round == round-half-to-even == rintf default mode.
    int pid = (int)rintf(p.x);
    int tid = (int)rintf(g.x);
    pid = min(max(pid, 0), NF_ - 1);
    tid = min(max(tid, 0), NF_ - 1);

    const float pamt = p.y;
    const float tamt = g.y;
    const float* __restrict__ dp = data + pid * NC_;
    const float* __restrict__ dt = data + tid * NC_;

    float diff[NC_];
    #pragma unroll
    for (int c = 0; c < NC_; c++)
        diff[c] = __ldg(dp + c) * pamt - __ldg(dt + c) * tamt;

    // Warp reduction (5 categories)
    #pragma unroll
    for (int off = 16; off > 0; off >>= 1) {
        #pragma unroll
        for (int c = 0; c < NC_; c++)
            diff[c] += __shfl_down_sync(0xffffffffu, diff[c], off);
    }
    if (lane == 0) {
        #pragma unroll
        for (int c = 0; c < NC_; c++) wsum[wid][c] = diff[c];
    }
    __syncthreads();

    // Cross-warp reduce + abs + category sum by thread 0 (fixed order).
    if (t == 0) {
        float s = 0.0f;
        #pragma unroll
        for (int c = 0; c < NC_; c++) {
            float a = 0.0f;
            #pragma unroll
            for (int w = 0; w < NWARPS; w++) a += wsum[w][c];
            s += fabsf(a);
        }
        g_partial[b] = s;

        // Publish, take a ticket; last block does the final reduction.
        __threadfence();
        unsigned int tk = atomicAdd(&g_ticket, 1u);
        s_islast = (tk == B_ - 1) ? 1u : 0u;
    }
    __syncthreads();

    if (s_islast && t == 0) {
        __threadfence();   // acquire: make all g_partial writes visible
        float s = 0.0f;
        volatile float* gp = g_partial;
        #pragma unroll
        for (int i = 0; i < B_; i++) s += gp[i];
        out[0] = s * (5.0f / (B_ * 100.0f * 7.0f));
        g_ticket = 0u;     // reset for the next graph replay
    }
}

extern "C" void kernel_launch(void* const* d_in, const int* in_sizes, int n_in,
                              void* d_out, int out_size) {
    const float* y_pred = (const float*)d_in[0];   // [B,D,M,S,2]
    const float* y      = (const float*)d_in[1];   // [B,D,M,S,2]
    const float* data   = (const float*)d_in[2];   // [NF,NC]
    float* out = (float*)d_out;

    nutrition_fused<<<B_, SLOTS>>>(y_pred, y, data, out);
}

// round 3
// speedup vs baseline: 1.0449x; 1.0150x over previous
#include <cuda_runtime.h>
#include <cuda_bf16.h>

// Problem constants (fixed by reference)
#define B_  64
#define D_  7
#define M_  4
#define S_  16
#define NF_ 1000
#define NC_ 5
#define SLOTS (D_ * M_ * S_)   // 448 slots per batch
#define NWARPS (SLOTS / 32)    // 14

// Deterministic scratch (device allocation is forbidden)
__device__ float g_partial[B_];
__device__ unsigned int g_ticket;   // zero-init; last block resets it each replay

// One block per batch element; one thread per (d,m,s) slot.
// Math: ids are exact integers after rounding, so the Gaussian soft lookup
// exp(-100*k^2) is a one-hot gather (tail weight ~3.7e-44 << 1e-3 tol).
// The 20KB table is staged in smem (all 64 blocks read the SAME lines, so
// only the first wave pays DRAM; rest are L2 hits), turning the 10
// lane-divergent gathers per thread into cheap LDS (~4-way conflicts)
// instead of ~32 L1tex wavefronts per LDG.
// Last-arriving block does the fixed-order cross-batch sum (deterministic).
__global__ __launch_bounds__(SLOTS)
void nutrition_fused(const float* __restrict__ y_pred,
                     const float* __restrict__ y,
                     const float* __restrict__ data,
                     float* __restrict__ out) {
    __shared__ float stab[NF_ * NC_];          // 20000 B
    __shared__ float wsum[NWARPS][NC_];
    __shared__ unsigned int s_islast;

    const int b = blockIdx.x;
    const int t = threadIdx.x;                 // 0..447
    const int lane = t & 31;
    const int wid  = t >> 5;

    // Kick off the per-slot loads FIRST so they overlap table staging.
    const float2 p = reinterpret_cast<const float2*>(y_pred)[b * SLOTS + t];
    const float2 g = reinterpret_cast<const float2*>(y)     [b * SLOTS + t];

    // Stage nutrition table with vector loads: 5000 floats = 1250 float4.
    {
        const float4* src = reinterpret_cast<const float4*>(data);
        float4* dst = reinterpret_cast<float4*>(stab);
        #pragma unroll
        for (int i = t; i < (NF_ * NC_) / 4; i += SLOTS) dst[i] = src[i];
        // tail: 5000 % 4 == 0, no remainder
    }
    __syncthreads();

    // jnp.round == round-half-to-even == rintf default mode.
    int pid = (int)rintf(p.x);
    int tid = (int)rintf(g.x);
    pid = min(max(pid, 0), NF_ - 1);
    tid = min(max(tid, 0), NF_ - 1);

    const float pamt = p.y;
    const float tamt = g.y;
    const float* dp = &stab[pid * NC_];
    const float* dt = &stab[tid * NC_];

    float diff[NC_];
    #pragma unroll
    for (int c = 0; c < NC_; c++)
        diff[c] = dp[c] * pamt - dt[c] * tamt;

    // Warp reduction (5 categories)
    #pragma unroll
    for (int off = 16; off > 0; off >>= 1) {
        #pragma unroll
        for (int c = 0; c < NC_; c++)
            diff[c] += __shfl_down_sync(0xffffffffu, diff[c], off);
    }
    if (lane == 0) {
        #pragma unroll
        for (int c = 0; c < NC_; c++) wsum[wid][c] = diff[c];
    }
    __syncthreads();

    // Cross-warp reduce + abs + category sum by thread 0 (fixed order).
    if (t == 0) {
        float s = 0.0f;
        #pragma unroll
        for (int c = 0; c < NC_; c++) {
            float a = 0.0f;
            #pragma unroll
            for (int w = 0; w < NWARPS; w++) a += wsum[w][c];
            s += fabsf(a);
        }
        g_partial[b] = s;

        __threadfence();
        unsigned int tk = atomicAdd(&g_ticket, 1u);
        s_islast = (tk == B_ - 1) ? 1u : 0u;
    }
    __syncthreads();

    if (s_islast && t == 0) {
        __threadfence();   // acquire: all g_partial writes visible
        float s = 0.0f;
        volatile float* gp = g_partial;
        #pragma unroll
        for (int i = 0; i < B_; i++) s += gp[i];
        out[0] = s * (5.0f / (B_ * 100.0f * 7.0f));
        g_ticket = 0u;     // reset for next graph replay
    }
}

extern "C" void kernel_launch(void* const* d_in, const int* in_sizes, int n_in,
                              void* d_out, int out_size) {
    const float* y_pred = (const float*)d_in[0];   // [B,D,M,S,2]
    const float* y      = (const float*)d_in[1];   // [B,D,M,S,2]
    const float* data   = (const float*)d_in[2];   // [NF,NC]
    float* out = (float*)d_out;

    nutrition_fused<<<B_, SLOTS>>>(y_pred, y, data, out);
}

// round 4
// speedup vs baseline: 1.3413x; 1.2837x over previous
#include <cuda_runtime.h>
#include <cuda_bf16.h>

// Problem constants (fixed by reference)
#define B_  64
#define D_  7
#define M_  4
#define S_  16
#define NF_ 1000
#define NC_ 5
#define SLOTS (D_ * M_ * S_)   // 448 slots per batch
#define NWARPS (SLOTS / 32)    // 14

// Per-batch sync slots: low 32 bits = float payload, bit 63 = ready flag.
// A single aligned 8-byte volatile store makes value+flag atomic -> no
// membar, no atomics needed. Collector resets slots each launch (graph
// replays are stream-ordered, so reset is race-free).
__device__ unsigned long long g_sync[B_];   // zero-initialized

// One block per batch element; one thread per (d,m,s) slot.
// Math: ids are exact integers after rounding, so the Gaussian soft lookup
// exp(-100*k^2) is a one-hot gather (tail weight ~3.7e-44 << 1e-3 tol) ->
// hard gather from an smem-staged 20KB table.
__global__ __launch_bounds__(SLOTS)
void nutrition_fused(const float* __restrict__ y_pred,
                     const float* __restrict__ y,
                     const float* __restrict__ data,
                     float* __restrict__ out) {
    __shared__ float stab[NF_ * NC_];          // 20000 B
    __shared__ float wsum[NWARPS][NC_];

    const int b = blockIdx.x;
    const int t = threadIdx.x;                 // 0..447
    const int lane = t & 31;
    const int wid  = t >> 5;

    // Per-slot loads first so they overlap table staging.
    const float2 p = reinterpret_cast<const float2*>(y_pred)[b * SLOTS + t];
    const float2 g = reinterpret_cast<const float2*>(y)     [b * SLOTS + t];

    // Stage nutrition table: 5000 floats = 1250 float4 (3 iters/thread).
    {
        const float4* src = reinterpret_cast<const float4*>(data);
        float4* dst = reinterpret_cast<float4*>(stab);
        #pragma unroll
        for (int i = t; i < (NF_ * NC_) / 4; i += SLOTS) dst[i] = src[i];
    }
    __syncthreads();

    // jnp.round == round-half-to-even == rintf default mode.
    int pid = (int)rintf(p.x);
    int tid = (int)rintf(g.x);
    pid = min(max(pid, 0), NF_ - 1);
    tid = min(max(tid, 0), NF_ - 1);

    const float* dp = &stab[pid * NC_];
    const float* dt = &stab[tid * NC_];

    float diff[NC_];
    #pragma unroll
    for (int c = 0; c < NC_; c++)
        diff[c] = dp[c] * p.y - dt[c] * g.y;

    // Warp reduction (5 categories)
    #pragma unroll
    for (int off = 16; off > 0; off >>= 1) {
        #pragma unroll
        for (int c = 0; c < NC_; c++)
            diff[c] += __shfl_down_sync(0xffffffffu, diff[c], off);
    }
    if (lane == 0) {
        #pragma unroll
        for (int c = 0; c < NC_; c++) wsum[wid][c] = diff[c];
    }
    __syncthreads();

    // Cross-warp reduce in warp 0 via shuffles (lanes >= NWARPS contribute 0),
    // then abs + category sum, then publish value+flag in ONE 64-bit store.
    if (wid == 0) {
        float v[NC_];
        #pragma unroll
        for (int c = 0; c < NC_; c++)
            v[c] = (lane < NWARPS) ? wsum[lane][c] : 0.0f;
        #pragma unroll
        for (int off = 8; off > 0; off >>= 1) {   // 14 lanes -> offsets 8,4,2,1
            #pragma unroll
            for (int c = 0; c < NC_; c++)
                v[c] += __shfl_down_sync(0xffffffffu, v[c], off);
        }
        if (lane == 0) {
            float s = 0.0f;
            #pragma unroll
            for (int c = 0; c < NC_; c++) s += fabsf(v[c]);
            unsigned long long pkt =
                (unsigned long long)__float_as_uint(s) | (1ull << 63);
            ((volatile unsigned long long*)g_sync)[b] = pkt;
        }
    }

    // Block 0, warp 0: collect all 64 partials (2 slots per lane, distinct
    // addresses -> parallel polls), fixed-tree reduce (deterministic),
    // write output, reset slots for the next replay.
    if (b == 0 && wid == 0) {
        volatile unsigned long long* gs = (volatile unsigned long long*)g_sync;
        unsigned long long v0, v1;
        do { v0 = gs[lane];      } while (!(v0 >> 63));
        do { v1 = gs[lane + 32]; } while (!(v1 >> 63));
        float s = __uint_as_float((unsigned)v0) + __uint_as_float((unsigned)v1);
        #pragma unroll
        for (int off = 16; off > 0; off >>= 1)
            s += __shfl_down_sync(0xffffffffu, s, off);
        if (lane == 0)
            out[0] = s * (5.0f / (B_ * 100.0f * 7.0f));
        gs[lane] = 0ull;
        gs[lane + 32] = 0ull;
    }
}

extern "C" void kernel_launch(void* const* d_in, const int* in_sizes, int n_in,
                              void* d_out, int out_size) {
    const float* y_pred = (const float*)d_in[0];   // [B,D,M,S,2]
    const float* y      = (const float*)d_in[1];   // [B,D,M,S,2]
    const float* data   = (const float*)d_in[2];   // [NF,NC]
    float* out = (float*)d_out;

    nutrition_fused<<<B_, SLOTS>>>(y_pred, y, data, out);
}

// round 5
// speedup vs baseline: 1.3478x; 1.0048x over previous
#include <cuda_runtime.h>
#include <cuda_bf16.h>

// Problem constants (fixed by reference)
#define B_  64
#define D_  7
#define M_  4
#define S_  16
#define NF_ 1000
#define NC_ 5
#define SLOTS (D_ * M_ * S_)   // 448 slots per batch
#define NWARPS (SLOTS / 32)    // 14
#define NBLK   32              // each block handles batches b and b+32

// Per-block sync slots: low 32 bits = float payload (sum over this block's
// TWO batches of sum_c|diff_c|), bit 63 = ready flag. One aligned 8-byte
// volatile store delivers value+flag atomically -> no membar, no atomics.
// Collector resets slots each launch (graph replays are stream-ordered).
__device__ unsigned long long g_sync[NBLK];   // zero-initialized

// Math: ids are exact integers after rounding, so the Gaussian soft lookup
// exp(-100*k^2) is a one-hot gather (tail weight ~3.7e-44 << 1e-3 tol) ->
// hard gather from an smem-staged 20KB table.
__global__ __launch_bounds__(SLOTS)
void nutrition_fused(const float* __restrict__ y_pred,
                     const float* __restrict__ y,
                     const float* __restrict__ data,
                     float* __restrict__ out) {
    __shared__ float stab[NF_ * NC_];            // 20000 B
    __shared__ float wsum[NWARPS][2 * NC_];      // 14 warps x (2 batches x 5 cats)

    const int b = blockIdx.x;                    // 0..31
    const int t = threadIdx.x;                   // 0..447
    const int lane = t & 31;
    const int wid  = t >> 5;

    // Issue all per-slot loads FIRST (MLP=4) so they overlap table staging.
    const float2* yp2 = reinterpret_cast<const float2*>(y_pred);
    const float2* yt2 = reinterpret_cast<const float2*>(y);
    const float2 p0 = yp2[b * SLOTS + t];
    const float2 g0 = yt2[b * SLOTS + t];
    const float2 p1 = yp2[(b + NBLK) * SLOTS + t];
    const float2 g1 = yt2[(b + NBLK) * SLOTS + t];

    // Stage nutrition table: 5000 floats = 1250 float4 (3 iters/thread).
    {
        const float4* src = reinterpret_cast<const float4*>(data);
        float4* dst = reinterpret_cast<float4*>(stab);
        #pragma unroll
        for (int i = t; i < (NF_ * NC_) / 4; i += SLOTS) dst[i] = src[i];
    }
    __syncthreads();

    // jnp.round == round-half-to-even == rintf default mode.
    int pid0 = min(max((int)rintf(p0.x), 0), NF_ - 1);
    int tid0 = min(max((int)rintf(g0.x), 0), NF_ - 1);
    int pid1 = min(max((int)rintf(p1.x), 0), NF_ - 1);
    int tid1 = min(max((int)rintf(g1.x), 0), NF_ - 1);

    float diff[2 * NC_];
    {
        const float* dp0 = &stab[pid0 * NC_];
        const float* dt0 = &stab[tid0 * NC_];
        const float* dp1 = &stab[pid1 * NC_];
        const float* dt1 = &stab[tid1 * NC_];
        #pragma unroll
        for (int c = 0; c < NC_; c++) {
            diff[c]       = dp0[c] * p0.y - dt0[c] * g0.y;
            diff[NC_ + c] = dp1[c] * p1.y - dt1[c] * g1.y;
        }
    }

    // Warp reduction (10 values: 2 batches x 5 categories)
    #pragma unroll
    for (int off = 16; off > 0; off >>= 1) {
        #pragma unroll
        for (int c = 0; c < 2 * NC_; c++)
            diff[c] += __shfl_down_sync(0xffffffffu, diff[c], off);
    }
    if (lane == 0) {
        #pragma unroll
        for (int c = 0; c < 2 * NC_; c++) wsum[wid][c] = diff[c];
    }
    __syncthreads();

    // Cross-warp reduce in warp 0 via shuffles, then abs per (batch,cat),
    // pre-sum both batches, publish value+flag in ONE 64-bit store.
    if (wid == 0) {
        float v[2 * NC_];
        #pragma unroll
        for (int c = 0; c < 2 * NC_; c++)
            v[c] = (lane < NWARPS) ? wsum[lane][c] : 0.0f;
        #pragma unroll
        for (int off = 8; off > 0; off >>= 1) {   // 14 lanes -> 8,4,2,1
            #pragma unroll
            for (int c = 0; c < 2 * NC_; c++)
                v[c] += __shfl_down_sync(0xffffffffu, v[c], off);
        }
        if (lane == 0) {
            float s = 0.0f;
            #pragma unroll
            for (int c = 0; c < 2 * NC_; c++) s += fabsf(v[c]);
            unsigned long long pkt =
                (unsigned long long)__float_as_uint(s) | (1ull << 63);
            ((volatile unsigned long long*)g_sync)[b] = pkt;
        }
    }

    // Block 0, warp 0: ONE poll round (one slot per lane, independent
    // addresses -> a single parallel L2 round trip after the last publish),
    // fixed-tree reduce (deterministic), write output, reset slots.
    if (b == 0 && wid == 0) {
        volatile unsigned long long* gs = (volatile unsigned long long*)g_sync;
        unsigned long long v;
        do { v = gs[lane]; } while (!(v >> 63));
        float s = __uint_as_float((unsigned)v);
        #pragma unroll
        for (int off = 16; off > 0; off >>= 1)
            s += __shfl_down_sync(0xffffffffu, s, off);
        if (lane == 0)
            out[0] = s * (5.0f / (B_ * 100.0f * 7.0f));
        gs[lane] = 0ull;
    }
}

extern "C" void kernel_launch(void* const* d_in, const int* in_sizes, int n_in,
                              void* d_out, int out_size) {
    const float* y_pred = (const float*)d_in[0];   // [B,D,M,S,2]
    const float* y      = (const float*)d_in[1];   // [B,D,M,S,2]
    const float* data   = (const float*)d_in[2];   // [NF,NC]
    float* out = (float*)d_out;

    nutrition_fused<<<NBLK, SLOTS>>>(y_pred, y, data, out);
}